// round 12
// baseline (speedup 1.0000x reference)
#include <cuda_runtime.h>

// Problem shape (fixed by reference setup_inputs)
#define BB 16
#define HH 256
#define WW 256
#define CC 128
#define C4 (CC / 4)          // 32 float4 per pixel

#define THRESH_PRED 0.3f
#define THRESH_TRUE 0.5f
#define PENALTY_WEIGHT 0.05f

__device__ __forceinline__ float max4(float4 v) {
    return fmaxf(fmaxf(v.x, v.y), fmaxf(v.z, v.w));
}

// Scan channels [start*4, 128) until the predicate resolves. Exact: the mask
// predicate max(ch) > T is monotone in the set of examined channels.
__device__ __forceinline__ bool scan_rest(const float4* __restrict__ p,
                                          unsigned base, float T, int start) {
    for (int i = start; i < C4; i++)
        if (max4(p[base + i]) > T) return true;
    return false;
}

// ---------------------------------------------------------------------------
// ONE block, 128 threads (4 warps -> 4 SMSPs issue loads in parallel).
// Thread = (batch = tid>>3, mask = (tid>>2)&1, side = tid&3) probes ONE
// border pixel and resolves it EXACTLY:
//   pred thread: 8-channel prefix  (2 independent LDG.128), miss 0.3^8  ~ 6.6e-5
//   expo thread: 16-channel prefix (4 independent LDG.128), miss 0.5^16 ~ 1.5e-5
// -> P(any thread takes the dependent escalation round) ~ 0.5% per run;
// escalation itself is exact (monotone predicate, full 128-channel scan).
//
// Fast path: all 128 probed pixels set => every side of every mask has a
// set pixel => both bboxes are exactly [0,0,H-1,W-1] for every batch =>
// every penalty term is identically zero => output is exactly 0.0f.
//
// Speculative store: thread 0 writes 0.0f BEFORE the vote (value doesn't
// depend on the vote; only its survival does). Fast path then just exits;
// the slow path overwrites out[0] with the full reference computation
// before any thread exits. Removes the STG from the dependent tail.
//
// Slow path (uniform block branch; needs a probed pixel truly unset across
// ALL 128 channels, p ~ 0.3^128 on this data; exact for arbitrary inputs):
// full short-circuit scan, sentinel bboxes, empty-mask fallback, reference
// penalty math.
// ---------------------------------------------------------------------------
__global__ __launch_bounds__(128, 1)
void bbox_kernel(const float4* __restrict__ pred,
                 const float4* __restrict__ expo,
                 float* __restrict__ out) {
    const int tid  = threadIdx.x;
    const int lane = tid & 31;
    const int b    = tid >> 3;              // batch 0..15
    const int mask = (tid >> 2) & 1;        // 0 = pred, 1 = expo
    const int side = tid & 3;

    // Speculative fast-path result; overwritten by the slow path if taken.
    if (tid == 0) out[0] = 0.0f;

    // Border probe pixel: side 0:(0,127) 1:(H-1,127) 2:(127,0) 3:(127,W-1)
    const int y = (side == 0) ? 0 : (side == 1) ? (HH - 1) : 127;
    const int x = (side == 2) ? 0 : (side == 3) ? (WW - 1) : 127;
    // 32-bit element index: max is 16*65536*32 = 2^25 float4 -> fits easily.
    const unsigned base = ((unsigned)b * (HH * WW) + (unsigned)y * WW + x) * C4;

    bool set;
    if (mask) {
        // expo: 16-channel prefix, 4 independent loads (one memory round)
        const float4 v0 = expo[base + 0];
        const float4 v1 = expo[base + 1];
        const float4 v2 = expo[base + 2];
        const float4 v3 = expo[base + 3];
        const float mm = fmaxf(fmaxf(max4(v0), max4(v1)),
                               fmaxf(max4(v2), max4(v3)));
        set = mm > THRESH_TRUE;
        if (!set) set = scan_rest(expo, base, THRESH_TRUE, 4);
    } else {
        // pred: 8-channel prefix, 2 independent loads
        const float4 v0 = pred[base + 0];
        const float4 v1 = pred[base + 1];
        set = fmaxf(max4(v0), max4(v1)) > THRESH_PRED;
        if (!set) set = scan_rest(pred, base, THRESH_PRED, 2);
    }

    // Hardware block-wide AND vote (BAR.RED) — uniform decision.
    if (__syncthreads_and(set ? 1 : 0)) {
        return;                             // out[0] == 0.0f, provably exact
    }

    // ======================= EXACT SLOW PATH ============================
    __shared__ int   s_box[BB][2][4];       // [ymin, xmin, ymax, xmax]
    __shared__ float s_pen[BB];

    if (tid < BB * 8) ((int*)s_box)[tid] = ((tid & 3) < 2) ? HH : -1;
    __syncthreads();

    for (int pair = 0; pair < 2 * BB; pair++) {
        const int fb = pair >> 1;
        const int fm = pair & 1;
        const float4* fp = fm ? expo : pred;
        const float   fT = fm ? THRESH_TRUE : THRESH_PRED;
        for (int t = 0; t < (HH * WW) / 128; t++) {
            const int idx = t * 128 + tid;                  // pixel in batch
            const unsigned pb = ((unsigned)fb * (HH * WW) + idx) * C4;
            bool s2 = (fmaxf(max4(fp[pb]), max4(fp[pb + 1])) > fT);
            if (!s2) s2 = scan_rest(fp, pb, fT, 2);
            const unsigned mk = __ballot_sync(0xffffffffu, s2);
            if (lane == 0 && mk) {
                const int yy = idx >> 8;                    // W = 256
                const int xb = (idx & (WW - 1)) & ~31;
                atomicMin(&s_box[fb][fm][0], yy);
                atomicMax(&s_box[fb][fm][2], yy);
                atomicMin(&s_box[fb][fm][1], xb + (__ffs(mk) - 1));
                atomicMax(&s_box[fb][fm][3], xb + (31 - __clz(mk)));
            }
        }
    }
    __syncthreads();

    if (tid < BB) {
        float bx[2][4];
        #pragma unroll
        for (int m = 0; m < 2; m++) {
            if (s_box[tid][m][2] < 0) {                     // empty mask
                bx[m][0] = 0.0f; bx[m][1] = 0.0f;
                bx[m][2] = 1.0f; bx[m][3] = 1.0f;
            } else {
                bx[m][0] = (float)s_box[tid][m][0];
                bx[m][1] = (float)s_box[tid][m][1];
                bx[m][2] = (float)s_box[tid][m][2];
                bx[m][3] = (float)s_box[tid][m][3];
            }
        }

        const float pred_area = (bx[0][2] - bx[0][0] + 1.0f) * (bx[0][3] - bx[0][1] + 1.0f);
        const float true_area = (bx[1][2] - bx[1][0] + 1.0f) * (bx[1][3] - bx[1][1] + 1.0f);
        const float area_penalty =
            fmaxf(pred_area - true_area, 0.0f) / (true_area + 1.0f);

        const float dy = (bx[0][0] + bx[0][2]) * 0.5f - (bx[1][0] + bx[1][2]) * 0.5f;
        const float dx = (bx[0][1] + bx[0][3]) * 0.5f - (bx[1][1] + bx[1][3]) * 0.5f;
        const float center_offset = sqrtf(dy * dy + dx * dx) * (1.0f / 20.0f);

        s_pen[tid] = area_penalty + center_offset;
    }
    __syncthreads();

    if (tid == 0) {
        float s = 0.0f;
        #pragma unroll
        for (int i = 0; i < BB; i++) s += s_pen[i];         // fixed order
        out[0] = PENALTY_WEIGHT * s * (1.0f / (float)BB);
    }
}

// ---------------------------------------------------------------------------
extern "C" void kernel_launch(void* const* d_in, const int* in_sizes, int n_in,
                              void* d_out, int out_size) {
    const float4* pred = (const float4*)d_in[0];   // prediction_probs
    const float4* expo = (const float4*)d_in[1];   // expected_onehot
    float* out = (float*)d_out;

    bbox_kernel<<<1, 128>>>(pred, expo, out);
}

// round 14
// speedup vs baseline: 1.5035x; 1.5035x over previous
#include <cuda_runtime.h>

// Problem shape (fixed by reference setup_inputs)
#define BB 16
#define HH 256
#define WW 256
#define CC 128
#define C4 (CC / 4)          // 32 float4 per pixel

#define THRESH_PRED 0.3f
#define THRESH_TRUE 0.5f
#define PENALTY_WEIGHT 0.05f

__device__ __forceinline__ float max4(float4 v) {
    return fmaxf(fmaxf(v.x, v.y), fmaxf(v.z, v.w));
}

// Scan channels [start*4, 128) until the predicate resolves. Exact: the mask
// predicate max(ch) > T is monotone in the set of examined channels.
__device__ __forceinline__ bool scan_rest(const float4* __restrict__ p,
                                          unsigned base, float T, int start) {
    for (int i = start; i < C4; i++)
        if (max4(p[base + i]) > T) return true;
    return false;
}

// ---------------------------------------------------------------------------
// ONE block, 128 threads. WARP-UNIFORM mask split:
//   tid in [0,64)   (warps 0-1): pred probes,  b = tid>>2,     side = tid&3
//   tid in [64,128) (warps 2-3): expo probes,  b = (tid-64)>>2, side = tid&3
// -> the pred/expo branch never diverges within a warp; each warp issues one
// straight-line load sequence (no BSSY/BSYNC on the fast path).
//
// Each thread probes ONE border pixel and resolves it EXACTLY:
//   pred: 8-channel prefix  (2 independent LDG.128), miss 0.3^8  ~ 6.6e-5
//   expo: 16-channel prefix (4 independent LDG.128), miss 0.5^16 ~ 1.5e-5
// -> P(any thread takes the dependent escalation round) ~ 0.5% per run;
// escalation itself is exact (monotone predicate, full 128-channel scan).
//
// Fast path: all 128 probed pixels set => every side of every mask has a
// set pixel => both bboxes are exactly [0,0,H-1,W-1] for every batch =>
// every penalty term is identically zero => output is exactly 0.0f.
// Speculative store of 0.0f before the vote (value is vote-independent;
// the slow path overwrites it before any thread exits).
//
// Slow path (uniform block branch; needs a probed pixel truly unset across
// ALL 128 channels, p ~ 0.3^128 on this data; exact for arbitrary inputs):
// full short-circuit scan, sentinel bboxes, empty-mask fallback, reference
// penalty math.
// ---------------------------------------------------------------------------
__global__ __launch_bounds__(128, 1)
void bbox_kernel(const float4* __restrict__ pred,
                 const float4* __restrict__ expo,
                 float* __restrict__ out) {
    const int tid  = threadIdx.x;
    const int lane = tid & 31;
    const int mask = tid >> 6;              // 0 = pred (warps 0-1), 1 = expo
    const int b    = (tid >> 2) & 15;       // batch 0..15 within each half
    const int side = tid & 3;

    // Speculative fast-path result; overwritten by the slow path if taken.
    if (tid == 0) out[0] = 0.0f;

    // Border probe pixel: side 0:(0,127) 1:(H-1,127) 2:(127,0) 3:(127,W-1)
    const int y = (side == 0) ? 0 : (side == 1) ? (HH - 1) : 127;
    const int x = (side == 2) ? 0 : (side == 3) ? (WW - 1) : 127;
    // 32-bit element index: max is 16*65536*32 = 2^25 float4 -> fits easily.
    const unsigned base = ((unsigned)b * (HH * WW) + (unsigned)y * WW + x) * C4;

    bool set;
    if (mask) {                             // warp-uniform branch
        // expo: 16-channel prefix, 4 independent loads (one memory round)
        const float4 v0 = expo[base + 0];
        const float4 v1 = expo[base + 1];
        const float4 v2 = expo[base + 2];
        const float4 v3 = expo[base + 3];
        const float mm = fmaxf(fmaxf(max4(v0), max4(v1)),
                               fmaxf(max4(v2), max4(v3)));
        set = mm > THRESH_TRUE;
        if (!set) set = scan_rest(expo, base, THRESH_TRUE, 4);
    } else {
        // pred: 8-channel prefix, 2 independent loads
        const float4 v0 = pred[base + 0];
        const float4 v1 = pred[base + 1];
        set = fmaxf(max4(v0), max4(v1)) > THRESH_PRED;
        if (!set) set = scan_rest(pred, base, THRESH_PRED, 2);
    }

    // Hardware block-wide AND vote (BAR.RED) — uniform decision.
    if (__syncthreads_and(set ? 1 : 0)) {
        return;                             // out[0] == 0.0f, provably exact
    }

    // ======================= EXACT SLOW PATH ============================
    __shared__ int   s_box[BB][2][4];       // [ymin, xmin, ymax, xmax]
    __shared__ float s_pen[BB];

    if (tid < BB * 8) ((int*)s_box)[tid] = ((tid & 3) < 2) ? HH : -1;
    __syncthreads();

    for (int pair = 0; pair < 2 * BB; pair++) {
        const int fb = pair >> 1;
        const int fm = pair & 1;
        const float4* fp = fm ? expo : pred;
        const float   fT = fm ? THRESH_TRUE : THRESH_PRED;
        for (int t = 0; t < (HH * WW) / 128; t++) {
            const int idx = t * 128 + tid;                  // pixel in batch
            const unsigned pb = ((unsigned)fb * (HH * WW) + idx) * C4;
            bool s2 = (fmaxf(max4(fp[pb]), max4(fp[pb + 1])) > fT);
            if (!s2) s2 = scan_rest(fp, pb, fT, 2);
            const unsigned mk = __ballot_sync(0xffffffffu, s2);
            if (lane == 0 && mk) {
                const int yy = idx >> 8;                    // W = 256
                const int xb = (idx & (WW - 1)) & ~31;
                atomicMin(&s_box[fb][fm][0], yy);
                atomicMax(&s_box[fb][fm][2], yy);
                atomicMin(&s_box[fb][fm][1], xb + (__ffs(mk) - 1));
                atomicMax(&s_box[fb][fm][3], xb + (31 - __clz(mk)));
            }
        }
    }
    __syncthreads();

    if (tid < BB) {
        float bx[2][4];
        #pragma unroll
        for (int m = 0; m < 2; m++) {
            if (s_box[tid][m][2] < 0) {                     // empty mask
                bx[m][0] = 0.0f; bx[m][1] = 0.0f;
                bx[m][2] = 1.0f; bx[m][3] = 1.0f;
            } else {
                bx[m][0] = (float)s_box[tid][m][0];
                bx[m][1] = (float)s_box[tid][m][1];
                bx[m][2] = (float)s_box[tid][m][2];
                bx[m][3] = (float)s_box[tid][m][3];
            }
        }

        const float pred_area = (bx[0][2] - bx[0][0] + 1.0f) * (bx[0][3] - bx[0][1] + 1.0f);
        const float true_area = (bx[1][2] - bx[1][0] + 1.0f) * (bx[1][3] - bx[1][1] + 1.0f);
        const float area_penalty =
            fmaxf(pred_area - true_area, 0.0f) / (true_area + 1.0f);

        const float dy = (bx[0][0] + bx[0][2]) * 0.5f - (bx[1][0] + bx[1][2]) * 0.5f;
        const float dx = (bx[0][1] + bx[0][3]) * 0.5f - (bx[1][1] + bx[1][3]) * 0.5f;
        const float center_offset = sqrtf(dy * dy + dx * dx) * (1.0f / 20.0f);

        s_pen[tid] = area_penalty + center_offset;
    }
    __syncthreads();

    if (tid == 0) {
        float s = 0.0f;
        #pragma unroll
        for (int i = 0; i < BB; i++) s += s_pen[i];         // fixed order
        out[0] = PENALTY_WEIGHT * s * (1.0f / (float)BB);
    }
}

// ---------------------------------------------------------------------------
extern "C" void kernel_launch(void* const* d_in, const int* in_sizes, int n_in,
                              void* d_out, int out_size) {
    const float4* pred = (const float4*)d_in[0];   // prediction_probs
    const float4* expo = (const float4*)d_in[1];   // expected_onehot
    float* out = (float*)d_out;

    bbox_kernel<<<1, 128>>>(pred, expo, out);
}